// round 3
// baseline (speedup 1.0000x reference)
#include <cuda_runtime.h>
#include <cuda_bf16.h>

#define S 8192
#define H 2048

// __device__ globals are zero-initialized at module load; the last-finishing
// block of finish_kernel resets them so every graph replay sees identical
// initial state.
__device__ float    g_u[H];          // u[k] = sum_j w[j] * W_att[j, H+k]; must be 0 at entry
__device__ float    g_scores[S];     // overwritten every run
__device__ unsigned g_max_key;       // ordered-uint max score key; must be 0 at entry
__device__ float    g_sum;           // exp-sum accumulator; must be 0 at entry
__device__ unsigned g_arrive;        // barrier arrival counter; must be 0 at entry
__device__ unsigned g_done;          // completion counter; must be 0 at entry

// Ordered-uint encoding: monotonic map float -> uint so atomicMax works.
__device__ __forceinline__ unsigned f2key(float f) {
    unsigned u = __float_as_uint(f);
    return (u & 0x80000000u) ? ~u : (u | 0x80000000u);
}
__device__ __forceinline__ float key2f(unsigned k) {
    return (k & 0x80000000u) ? __uint_as_float(k ^ 0x80000000u)
                             : __uint_as_float(~k);
}

// ---------------------------------------------------------------------------
// Kernel 1: u[k] = sum_j w[j] * W_att[j*2H + H + k]
// 512 blocks = 8 k-tiles x 64 j-chunks of 32 rows. One atomicAdd per thread.
// ---------------------------------------------------------------------------
__global__ void __launch_bounds__(256) u_kernel(const float* __restrict__ W_att,
                                                const float* __restrict__ w) {
    const int k  = (blockIdx.x & 7) * 256 + threadIdx.x;
    const int j0 = (blockIdx.x >> 3) * 32;
    const float* base = W_att + (size_t)j0 * (2 * H) + H + k;
    float acc = 0.0f;
#pragma unroll 8
    for (int jj = 0; jj < 32; jj++)
        acc += w[j0 + jj] * base[(size_t)jj * (2 * H)];
    atomicAdd(&g_u[k], acc);
}

// ---------------------------------------------------------------------------
// Kernel 2: scores[s] = dot(enc[s], u) for 8 rows per block + global max.
// u-slice lives in registers; 16 independent LDG.128 per thread.
// ---------------------------------------------------------------------------
#define ROWS_PER_BLK 8
__global__ void __launch_bounds__(256) score_kernel(const float* __restrict__ enc) {
    const int t    = threadIdx.x;
    const int row0 = blockIdx.x * ROWS_PER_BLK;

    const float4* up = reinterpret_cast<const float4*>(g_u) + t * 2;
    const float4 u0 = up[0], u1 = up[1];

    float acc[ROWS_PER_BLK];
#pragma unroll
    for (int r = 0; r < ROWS_PER_BLK; r++) {
        const float4* e = reinterpret_cast<const float4*>(
                              enc + (size_t)(row0 + r) * H) + t * 2;
        const float4 e0 = e[0], e1 = e[1];
        acc[r] = e0.x * u0.x + e0.y * u0.y + e0.z * u0.z + e0.w * u0.w
               + e1.x * u1.x + e1.y * u1.y + e1.z * u1.z + e1.w * u1.w;
    }

    __shared__ float sm[8][ROWS_PER_BLK];   // [warp][row]
    const int lane = t & 31, wid = t >> 5;
#pragma unroll
    for (int r = 0; r < ROWS_PER_BLK; r++) {
        float v = acc[r];
#pragma unroll
        for (int off = 16; off > 0; off >>= 1)
            v += __shfl_down_sync(0xffffffffu, v, off);
        if (lane == 0) sm[wid][r] = v;
    }
    __syncthreads();

    if (wid == 0) {
        float v = 0.0f;
        if (lane < ROWS_PER_BLK) {
#pragma unroll
            for (int w8 = 0; w8 < 8; w8++) v += sm[w8][lane];
            g_scores[row0 + lane] = v;
        }
        float m = (lane < ROWS_PER_BLK) ? v : -3.0e38f;
#pragma unroll
        for (int off = 16; off > 0; off >>= 1)
            m = fmaxf(m, __shfl_xor_sync(0xffffffffu, m, off));
        if (lane == 0) atomicMax(&g_max_key, f2key(m));
    }
}

// ---------------------------------------------------------------------------
// Kernel 3 (fused): exp + global sum (software grid barrier) + normalize +
// state reset. 32 blocks x 256 threads, one element per thread; the exp value
// stays in a register across the barrier so out is written exactly once.
// 32 blocks always co-resident on 148 SMs -> spin barrier is deadlock-free.
// ---------------------------------------------------------------------------
__global__ void __launch_bounds__(256) finish_kernel(float* __restrict__ out) {
    const int t = threadIdx.x;
    const int s = blockIdx.x * 256 + t;

    const float mx = key2f(g_max_key);
    const float e  = expf(g_scores[s] - mx);

    // block partial sum
    float v = e;
#pragma unroll
    for (int off = 16; off > 0; off >>= 1)
        v += __shfl_down_sync(0xffffffffu, v, off);

    __shared__ float sm[8];
    const int lane = t & 31, wid = t >> 5;
    if (lane == 0) sm[wid] = v;
    __syncthreads();
    if (t == 0) {
        float p = 0.0f;
#pragma unroll
        for (int w8 = 0; w8 < 8; w8++) p += sm[w8];
        atomicAdd(&g_sum, p);          // release the partial sum
        __threadfence();
        atomicAdd(&g_arrive, 1u);      // arrive at the grid barrier
        // spin until all 32 blocks have arrived
        while (*(volatile unsigned*)&g_arrive < 32u) { }
    }
    __syncthreads();                   // broadcast barrier passage to the block
    __threadfence();                   // acquire: make g_sum writes visible

    const float inv = 1.0f / (*(volatile float*)&g_sum);
    out[s] = e * inv;

    // ---- last-block-done state reset (safe: all other blocks have finished
    // their final store before the 32nd g_done increment can land) ----
    __syncthreads();
    __shared__ unsigned s_last;
    if (t == 0) {
        __threadfence();
        s_last = (atomicAdd(&g_done, 1u) == 31u) ? 1u : 0u;
    }
    __syncthreads();
    if (s_last) {
#pragma unroll
        for (int i = 0; i < H / 256; i++)
            g_u[t + i * 256] = 0.0f;
        if (t == 0) {
            g_max_key = 0u;
            g_sum     = 0.0f;
            g_arrive  = 0u;
            g_done    = 0u;
        }
    }
}

// ---------------------------------------------------------------------------
// Inputs (metadata order): encoder_outputs (S*1*H), hidden (H),
//                          W_att (H*2H), b_att (H), w (1*H)
// hidden / b_att / left half of W_att drop out (softmax shift invariance).
// ---------------------------------------------------------------------------
extern "C" void kernel_launch(void* const* d_in, const int* in_sizes, int n_in,
                              void* d_out, int out_size) {
    const float* enc   = (const float*)d_in[0];
    const float* W_att = (const float*)d_in[2];
    const float* w     = (const float*)d_in[4];
    float* out = (float*)d_out;

    u_kernel<<<512, 256>>>(W_att, w);
    score_kernel<<<S / ROWS_PER_BLK, 256>>>(enc);
    finish_kernel<<<32, 256>>>(out);
}